// round 12
// baseline (speedup 1.0000x reference)
#include <cuda_runtime.h>
#include <cuda_bf16.h>
#include <cstdint>

#define N_NODES 50000
#define N_EDGES_MAX 600000
#define D 128
#define N_CLASSES 40

#define SCAN_BLK 1024
#define SCAN_NBLK ((N_NODES + SCAN_BLK - 1) / SCAN_BLK)   // 49

// Scratch (static device globals — no allocations allowed).
// Only dereferenced from DEVICE code; host only takes addresses via API.
__device__ float g_acc[N_NODES * D];   // z = h W^T (GEMM output / gather input)
__device__ float g_buf0[N_NODES * D];  // layer activations ping
__device__ float g_buf1[N_NODES * D];  // layer activations pong
__device__ int   g_cnt[N_NODES];
__device__ int   g_row[N_NODES + 1];
__device__ int   g_cur[N_NODES];
__device__ int   g_esrc[N_EDGES_MAX];
__device__ int   g_bsum[SCAN_NBLK];

// ---------------------------------------------------------------------------
// CSR build (4 edges per thread)
// ---------------------------------------------------------------------------
__global__ void gcn_hist_kernel(const int* __restrict__ dst, int n_edges) {
    int e0 = (blockIdx.x * blockDim.x + threadIdx.x) * 4;
    if (e0 + 3 < n_edges) {
        int4 d = *(const int4*)(dst + e0);
        atomicAdd(&g_cnt[d.x], 1);
        atomicAdd(&g_cnt[d.y], 1);
        atomicAdd(&g_cnt[d.z], 1);
        atomicAdd(&g_cnt[d.w], 1);
    } else {
        for (int e = e0; e < n_edges; e++) atomicAdd(&g_cnt[dst[e]], 1);
    }
}

__global__ void gcn_scanA_kernel() {
    __shared__ int sh[SCAN_BLK];
    int t = threadIdx.x;
    int idx = blockIdx.x * SCAN_BLK + t;
    int v = (idx < N_NODES) ? g_cnt[idx] : 0;
    sh[t] = v;
    __syncthreads();
    for (int off = 1; off < SCAN_BLK; off <<= 1) {
        int u = (t >= off) ? sh[t - off] : 0;
        __syncthreads();
        sh[t] += u;
        __syncthreads();
    }
    if (idx < N_NODES) g_row[idx] = sh[t] - v;
    if (t == SCAN_BLK - 1) g_bsum[blockIdx.x] = sh[t];
}

__global__ void gcn_scanB_kernel() {
    __shared__ int sh[64];
    __shared__ int s_off;
    int t = threadIdx.x;
    int blk = blockIdx.x;
    if (t < 64) sh[t] = (t < SCAN_NBLK) ? g_bsum[t] : 0;
    __syncthreads();
    if (t == 0) {
        int o = 0;
#pragma unroll 7
        for (int b = 0; b < blk; b++) o += sh[b];
        s_off = o;
    }
    __syncthreads();
    int off = s_off;
    int idx = blk * SCAN_BLK + t;
    if (idx < N_NODES) {
        int r = g_row[idx] + off;
        g_row[idx] = r;
        g_cur[idx] = r;
        if (idx == N_NODES - 1) g_row[N_NODES] = r + g_cnt[idx];
    }
}

__global__ void gcn_fill_kernel(const int* __restrict__ src,
                                const int* __restrict__ dst, int n_edges) {
    int e0 = (blockIdx.x * blockDim.x + threadIdx.x) * 4;
    if (e0 + 3 < n_edges) {
        int4 s = *(const int4*)(src + e0);
        int4 d = *(const int4*)(dst + e0);
        int p0 = atomicAdd(&g_cur[d.x], 1);
        int p1 = atomicAdd(&g_cur[d.y], 1);
        int p2 = atomicAdd(&g_cur[d.z], 1);
        int p3 = atomicAdd(&g_cur[d.w], 1);
        g_esrc[p0] = s.x; g_esrc[p1] = s.y; g_esrc[p2] = s.z; g_esrc[p3] = s.w;
    } else {
        for (int e = e0; e < n_edges; e++) {
            int pos = atomicAdd(&g_cur[dst[e]], 1);
            g_esrc[pos] = src[e];
        }
    }
}

// ---------------------------------------------------------------------------
// Buffer selection by template (device-symbol addresses stay device-side).
// SEL: 0 = param pointer, 1 = g_buf0, 2 = g_buf1
// ---------------------------------------------------------------------------
template <int SEL>
__device__ __forceinline__ const float* sel_in(const float* p) {
    if (SEL == 0) return p;
    if (SEL == 1) return g_buf0;
    return g_buf1;
}
template <int SEL>
__device__ __forceinline__ float* sel_out(float* p) {
    if (SEL == 0) return p;
    if (SEL == 1) return g_buf0;
    return g_buf1;
}

// ---------------------------------------------------------------------------
// GEMM column-chunk: z[:, j0:j0+BN] = in @ W[j0:j0+BN]^T (no bias/act).
// K-paired FFMA2. BN=64 -> 67.5KB smem -> 3 CTAs/SM.
// ---------------------------------------------------------------------------
template <int INSEL, int BN, int TN>
__global__ __launch_bounds__(256, 3)
void gcn_gemm_kernel(const float* __restrict__ in_p,
                     const float* __restrict__ W,
                     int n_out, int ldz, int j0) {
    constexpr int BM = 64;
    constexpr int K = D;
    constexpr int LDA = K + 4;
    constexpr int LDK = K + 4;
    extern __shared__ float sm[];
    float* As = sm;               // [BM][LDA]
    float* Bs = sm + BM * LDA;    // [BN][LDK]

    const float* in = sel_in<INSEL>(in_p);
    int tid = threadIdx.x;
    int row0 = blockIdx.x * BM;

    for (int i = tid * 4; i < BN * K; i += 256 * 4) {
        int j = i / K, k = i % K;
        float4 v = (j0 + j < n_out) ? *(const float4*)(W + (size_t)(j0 + j) * K + k)
                                    : make_float4(0.f, 0.f, 0.f, 0.f);
        *(float4*)(Bs + j * LDK + k) = v;
    }
    for (int i = tid * 4; i < BM * K; i += 256 * 4) {
        int r = i / K, k = i % K;
        int g = row0 + r;
        float4 v = (g < N_NODES) ? *(const float4*)(in + (size_t)g * K + k)
                                 : make_float4(0.f, 0.f, 0.f, 0.f);
        *(float4*)(As + r * LDA + k) = v;
    }
    __syncthreads();

    int tc = tid & 15;
    int tr = tid >> 4;

    unsigned long long acc[4][TN];
#pragma unroll
    for (int ii = 0; ii < 4; ii++)
#pragma unroll
        for (int jj = 0; jj < TN; jj++) acc[ii][jj] = 0ULL;

#pragma unroll 2
    for (int k = 0; k < K; k += 4) {
        ulonglong2 ap[4];
#pragma unroll
        for (int ii = 0; ii < 4; ii++)
            ap[ii] = *(const ulonglong2*)(As + (tr * 4 + ii) * LDA + k);
#pragma unroll
        for (int jg = 0; jg < TN; jg += 4) {
            ulonglong2 bp[4];
#pragma unroll
            for (int j4 = 0; j4 < 4; j4++)
                bp[j4] = *(const ulonglong2*)(Bs + (tc + 16 * (jg + j4)) * LDK + k);
#pragma unroll
            for (int ii = 0; ii < 4; ii++)
#pragma unroll
                for (int j4 = 0; j4 < 4; j4++) {
                    asm("fma.rn.f32x2 %0, %1, %2, %0;"
                        : "+l"(acc[ii][jg + j4]) : "l"(ap[ii].x), "l"(bp[j4].x));
                    asm("fma.rn.f32x2 %0, %1, %2, %0;"
                        : "+l"(acc[ii][jg + j4]) : "l"(ap[ii].y), "l"(bp[j4].y));
                }
        }
    }

#pragma unroll
    for (int ii = 0; ii < 4; ii++) {
        int g = row0 + tr * 4 + ii;
        if (g >= N_NODES) continue;
#pragma unroll
        for (int jj = 0; jj < TN; jj++) {
            int j = j0 + tc + 16 * jj;
            if (j >= n_out) continue;
            float lo, hi;
            asm("mov.b64 {%0, %1}, %2;" : "=f"(lo), "=f"(hi) : "l"(acc[ii][jj]));
            g_acc[(size_t)g * ldz + j] = lo + hi;
        }
    }
}

// ---------------------------------------------------------------------------
// Gather column-chunk over z, fused bias + activation:
//   out[n, c0+c] = act( z[n, c0+c] + sum_{s in nbrs(n)} z[s, c0+c] + b[c0+c] )
// LD = row stride; NV = active float4 lanes (16 for 64-col chunk, 10 for head).
// ---------------------------------------------------------------------------
template <int OUTSEL, int LD, int NV, bool RELU>
__global__ void gcn_gather_kernel(const float* __restrict__ bias,
                                  float* __restrict__ out_p, int c0) {
    int node = blockIdx.x * (blockDim.x >> 5) + (threadIdx.x >> 5);
    if (node >= N_NODES) return;
    int lane = threadIdx.x & 31;
    bool act = (NV == 32) || (lane < NV);
    int col = c0 + lane * 4;
    int beg = g_row[node];
    int end = g_row[node + 1];

    float4 acc = make_float4(0.f, 0.f, 0.f, 0.f);
    float4 bv = make_float4(0.f, 0.f, 0.f, 0.f);
    if (act) {
        acc = *(const float4*)(g_acc + (size_t)node * LD + col);  // self
        bv = *(const float4*)(bias + col);
    }
    int i = beg;
    for (; i + 4 <= end; i += 4) {
        int s0 = g_esrc[i], s1 = g_esrc[i + 1], s2 = g_esrc[i + 2], s3 = g_esrc[i + 3];
        if (act) {
            float4 v0 = *(const float4*)(g_acc + (size_t)s0 * LD + col);
            float4 v1 = *(const float4*)(g_acc + (size_t)s1 * LD + col);
            float4 v2 = *(const float4*)(g_acc + (size_t)s2 * LD + col);
            float4 v3 = *(const float4*)(g_acc + (size_t)s3 * LD + col);
            acc.x += v0.x + v1.x + v2.x + v3.x;
            acc.y += v0.y + v1.y + v2.y + v3.y;
            acc.z += v0.z + v1.z + v2.z + v3.z;
            acc.w += v0.w + v1.w + v2.w + v3.w;
        }
    }
    for (; i < end; i++) {
        int s = g_esrc[i];
        if (act) {
            float4 v = *(const float4*)(g_acc + (size_t)s * LD + col);
            acc.x += v.x; acc.y += v.y; acc.z += v.z; acc.w += v.w;
        }
    }
    if (act) {
        acc.x += bv.x; acc.y += bv.y; acc.z += bv.z; acc.w += bv.w;
        if (RELU) {
            acc.x = fmaxf(acc.x, 0.f); acc.y = fmaxf(acc.y, 0.f);
            acc.z = fmaxf(acc.z, 0.f); acc.w = fmaxf(acc.w, 0.f);
        }
        float* outp = sel_out<OUTSEL>(out_p);
        *(float4*)(outp + (size_t)node * LD + col) = acc;
    }
}

// ---------------------------------------------------------------------------
extern "C" void kernel_launch(void* const* d_in, const int* in_sizes, int n_in,
                              void* d_out, int out_size) {
    const float* x  = (const float*)d_in[0];
    const int* src  = (const int*)d_in[1];
    const int* dst  = (const int*)d_in[2];
    const float* W0 = (const float*)d_in[3];
    const float* b0 = (const float*)d_in[4];
    const float* W1 = (const float*)d_in[5];
    const float* b1 = (const float*)d_in[6];
    const float* W2 = (const float*)d_in[7];
    const float* b2 = (const float*)d_in[8];
    float* out = (float*)d_out;
    int n_edges = in_sizes[1];

    constexpr int SMEM_HALF = (64 * 132 + 64 * 132) * 4;   // 67584 B -> 3 CTA/SM
    static cudaStream_t s1 = nullptr;
    static cudaEvent_t e_fork = nullptr, e_csr = nullptr;
    static cudaEvent_t eA0, eA1, eB0, eB1;
    if (!s1) {
        cudaFuncSetAttribute(gcn_gemm_kernel<0, 64, 4>,
                             cudaFuncAttributeMaxDynamicSharedMemorySize, SMEM_HALF);
        cudaFuncSetAttribute(gcn_gemm_kernel<1, 64, 4>,
                             cudaFuncAttributeMaxDynamicSharedMemorySize, SMEM_HALF);
        cudaFuncSetAttribute(gcn_gemm_kernel<2, 64, 4>,
                             cudaFuncAttributeMaxDynamicSharedMemorySize, SMEM_HALF);
        cudaStreamCreateWithFlags(&s1, cudaStreamNonBlocking);
        cudaEventCreateWithFlags(&e_fork, cudaEventDisableTiming);
        cudaEventCreateWithFlags(&e_csr, cudaEventDisableTiming);
        cudaEventCreateWithFlags(&eA0, cudaEventDisableTiming);
        cudaEventCreateWithFlags(&eA1, cudaEventDisableTiming);
        cudaEventCreateWithFlags(&eB0, cudaEventDisableTiming);
        cudaEventCreateWithFlags(&eB1, cudaEventDisableTiming);
    }

    void* cnt_ptr = nullptr;
    cudaGetSymbolAddress(&cnt_ptr, g_cnt);

    int hist_blocks = ((n_edges + 3) / 4 + 255) / 256;
    int gath_blocks = (N_NODES + 7) / 8;
    int gemm_blocks = (N_NODES + 63) / 64;

    // Fork: CSR build on s1, concurrent with GEMM0 on the origin stream.
    cudaEventRecord(e_fork, 0);
    cudaStreamWaitEvent(s1, e_fork, 0);
    cudaMemsetAsync(cnt_ptr, 0, N_NODES * sizeof(int), s1);
    gcn_hist_kernel<<<hist_blocks, 256, 0, s1>>>(dst, n_edges);
    gcn_scanA_kernel<<<SCAN_NBLK, SCAN_BLK, 0, s1>>>();
    gcn_scanB_kernel<<<SCAN_NBLK, SCAN_BLK, 0, s1>>>();
    gcn_fill_kernel<<<hist_blocks, 256, 0, s1>>>(src, dst, n_edges);
    cudaEventRecord(e_csr, s1);

    // ---- Layer 0: x -> z (split cols) -> h1 (g_buf0) ----
    gcn_gemm_kernel<0, 64, 4><<<gemm_blocks, 256, SMEM_HALF>>>(x, W0, D, D, 0);
    cudaEventRecord(eA0, 0);
    gcn_gemm_kernel<0, 64, 4><<<gemm_blocks, 256, SMEM_HALF>>>(x, W0, D, D, 64);
    // gather_lo on s1 (after CSR by s1 ordering, after GEMM_lo via eA0)
    cudaStreamWaitEvent(s1, eA0, 0);
    gcn_gather_kernel<1, 128, 16, true><<<gath_blocks, 256, 0, s1>>>(b0, nullptr, 0);
    cudaEventRecord(eB0, s1);
    // gather_hi on main (needs CSR)
    cudaStreamWaitEvent(0, e_csr, 0);
    gcn_gather_kernel<1, 128, 16, true><<<gath_blocks, 256>>>(b0, nullptr, 64);
    cudaStreamWaitEvent(0, eB0, 0);

    // ---- Layer 1: h1 -> z (split cols) -> h2 (g_buf1) ----
    gcn_gemm_kernel<1, 64, 4><<<gemm_blocks, 256, SMEM_HALF>>>(nullptr, W1, D, D, 0);
    cudaEventRecord(eA1, 0);
    gcn_gemm_kernel<1, 64, 4><<<gemm_blocks, 256, SMEM_HALF>>>(nullptr, W1, D, D, 64);
    cudaStreamWaitEvent(s1, eA1, 0);
    gcn_gather_kernel<2, 128, 16, true><<<gath_blocks, 256, 0, s1>>>(b1, nullptr, 0);
    cudaEventRecord(eB1, s1);
    gcn_gather_kernel<2, 128, 16, true><<<gath_blocks, 256>>>(b1, nullptr, 64);
    cudaStreamWaitEvent(0, eB1, 0);

    // ---- Layer 2 (head): h2 -> z (40-wide) -> out ----
    gcn_gemm_kernel<2, 64, 4><<<gemm_blocks, 256, SMEM_HALF>>>(
        nullptr, W2, N_CLASSES, N_CLASSES, 0);
    gcn_gather_kernel<0, N_CLASSES, 10, false><<<gath_blocks, 256>>>(b2, out, 0);
}

// round 14
// speedup vs baseline: 1.0786x; 1.0786x over previous
#include <cuda_runtime.h>
#include <cuda_bf16.h>
#include <cstdint>

#define N_NODES 50000
#define N_EDGES_MAX 600000
#define D 128
#define N_CLASSES 40
#define HALF_N 25024   // row-split point (multiple of 64)

#define SCAN_BLK 1024
#define SCAN_NBLK ((N_NODES + SCAN_BLK - 1) / SCAN_BLK)   // 49

// Scratch (static device globals — no allocations allowed).
// Only dereferenced from DEVICE code; host only takes addresses via API.
__device__ float g_accA[N_NODES * D];  // z ping (layers 0, 2)
__device__ float g_accB[N_NODES * D];  // z pong (layer 1)
__device__ float g_buf0[N_NODES * D];  // h1
__device__ float g_buf1[N_NODES * D];  // h2
__device__ int   g_cnt[N_NODES];
__device__ int   g_row[N_NODES + 1];
__device__ int   g_cur[N_NODES];
__device__ int   g_esrc[N_EDGES_MAX];
__device__ int   g_bsum[SCAN_NBLK];

// ---------------------------------------------------------------------------
// CSR build (4 edges per thread)
// ---------------------------------------------------------------------------
__global__ void gcn_hist_kernel(const int* __restrict__ dst, int n_edges) {
    int e0 = (blockIdx.x * blockDim.x + threadIdx.x) * 4;
    if (e0 + 3 < n_edges) {
        int4 d = *(const int4*)(dst + e0);
        atomicAdd(&g_cnt[d.x], 1);
        atomicAdd(&g_cnt[d.y], 1);
        atomicAdd(&g_cnt[d.z], 1);
        atomicAdd(&g_cnt[d.w], 1);
    } else {
        for (int e = e0; e < n_edges; e++) atomicAdd(&g_cnt[dst[e]], 1);
    }
}

__global__ void gcn_scanA_kernel() {
    __shared__ int sh[SCAN_BLK];
    int t = threadIdx.x;
    int idx = blockIdx.x * SCAN_BLK + t;
    int v = (idx < N_NODES) ? g_cnt[idx] : 0;
    sh[t] = v;
    __syncthreads();
    for (int off = 1; off < SCAN_BLK; off <<= 1) {
        int u = (t >= off) ? sh[t - off] : 0;
        __syncthreads();
        sh[t] += u;
        __syncthreads();
    }
    if (idx < N_NODES) g_row[idx] = sh[t] - v;
    if (t == SCAN_BLK - 1) g_bsum[blockIdx.x] = sh[t];
}

__global__ void gcn_scanB_kernel() {
    __shared__ int sh[64];
    __shared__ int s_off;
    int t = threadIdx.x;
    int blk = blockIdx.x;
    if (t < 64) sh[t] = (t < SCAN_NBLK) ? g_bsum[t] : 0;
    __syncthreads();
    if (t == 0) {
        int o = 0;
#pragma unroll 7
        for (int b = 0; b < blk; b++) o += sh[b];
        s_off = o;
    }
    __syncthreads();
    int off = s_off;
    int idx = blk * SCAN_BLK + t;
    if (idx < N_NODES) {
        int r = g_row[idx] + off;
        g_row[idx] = r;
        g_cur[idx] = r;
        if (idx == N_NODES - 1) g_row[N_NODES] = r + g_cnt[idx];
    }
}

__global__ void gcn_fill_kernel(const int* __restrict__ src,
                                const int* __restrict__ dst, int n_edges) {
    int e0 = (blockIdx.x * blockDim.x + threadIdx.x) * 4;
    if (e0 + 3 < n_edges) {
        int4 s = *(const int4*)(src + e0);
        int4 d = *(const int4*)(dst + e0);
        int p0 = atomicAdd(&g_cur[d.x], 1);
        int p1 = atomicAdd(&g_cur[d.y], 1);
        int p2 = atomicAdd(&g_cur[d.z], 1);
        int p3 = atomicAdd(&g_cur[d.w], 1);
        g_esrc[p0] = s.x; g_esrc[p1] = s.y; g_esrc[p2] = s.z; g_esrc[p3] = s.w;
    } else {
        for (int e = e0; e < n_edges; e++) {
            int pos = atomicAdd(&g_cur[dst[e]], 1);
            g_esrc[pos] = src[e];
        }
    }
}

// ---------------------------------------------------------------------------
// Buffer selection by template (device-symbol addresses stay device-side).
// IN/OUT SEL: 0 = param pointer, 1 = g_buf0, 2 = g_buf1
// ZSEL:       0 = g_accA, 1 = g_accB
// ---------------------------------------------------------------------------
template <int SEL>
__device__ __forceinline__ const float* sel_in(const float* p) {
    if (SEL == 0) return p;
    if (SEL == 1) return g_buf0;
    return g_buf1;
}
template <int SEL>
__device__ __forceinline__ float* sel_out(float* p) {
    if (SEL == 0) return p;
    if (SEL == 1) return g_buf0;
    return g_buf1;
}
template <int ZSEL>
__device__ __forceinline__ float* sel_z() {
    return (ZSEL == 0) ? g_accA : g_accB;
}

// ---------------------------------------------------------------------------
// GEMM over a row range: z[row_base+., :n_out] = in @ W^T (no bias/act).
// K-paired FFMA2, BN=128 -> 101KB smem -> 2 CTAs/SM; BN=64 head -> 67.5KB.
// ---------------------------------------------------------------------------
template <int INSEL, int ZSEL, int BN, int TN>
__global__ __launch_bounds__(256, 2)
void gcn_gemm_kernel(const float* __restrict__ in_p,
                     const float* __restrict__ W,
                     int n_out, int ldz, int row_base) {
    constexpr int BM = 64;
    constexpr int K = D;
    constexpr int LDA = K + 4;
    constexpr int LDK = K + 4;
    extern __shared__ float sm[];
    float* As = sm;               // [BM][LDA]
    float* Bs = sm + BM * LDA;    // [BN][LDK]

    const float* in = sel_in<INSEL>(in_p);
    float* z = sel_z<ZSEL>();
    int tid = threadIdx.x;
    int row0 = row_base + blockIdx.x * BM;

    for (int i = tid * 4; i < BN * K; i += 256 * 4) {
        int j = i / K, k = i % K;
        float4 v = (j < n_out) ? *(const float4*)(W + (size_t)j * K + k)
                               : make_float4(0.f, 0.f, 0.f, 0.f);
        *(float4*)(Bs + j * LDK + k) = v;
    }
    for (int i = tid * 4; i < BM * K; i += 256 * 4) {
        int r = i / K, k = i % K;
        int g = row0 + r;
        float4 v = (g < N_NODES) ? *(const float4*)(in + (size_t)g * K + k)
                                 : make_float4(0.f, 0.f, 0.f, 0.f);
        *(float4*)(As + r * LDA + k) = v;
    }
    __syncthreads();

    int tc = tid & 15;
    int tr = tid >> 4;

    unsigned long long acc[4][TN];
#pragma unroll
    for (int ii = 0; ii < 4; ii++)
#pragma unroll
        for (int jj = 0; jj < TN; jj++) acc[ii][jj] = 0ULL;

#pragma unroll 2
    for (int k = 0; k < K; k += 4) {
        ulonglong2 ap[4];
#pragma unroll
        for (int ii = 0; ii < 4; ii++)
            ap[ii] = *(const ulonglong2*)(As + (tr * 4 + ii) * LDA + k);
#pragma unroll
        for (int jg = 0; jg < TN; jg += 4) {
            ulonglong2 bp[4];
#pragma unroll
            for (int j4 = 0; j4 < 4; j4++)
                bp[j4] = *(const ulonglong2*)(Bs + (tc + 16 * (jg + j4)) * LDK + k);
#pragma unroll
            for (int ii = 0; ii < 4; ii++)
#pragma unroll
                for (int j4 = 0; j4 < 4; j4++) {
                    asm("fma.rn.f32x2 %0, %1, %2, %0;"
                        : "+l"(acc[ii][jg + j4]) : "l"(ap[ii].x), "l"(bp[j4].x));
                    asm("fma.rn.f32x2 %0, %1, %2, %0;"
                        : "+l"(acc[ii][jg + j4]) : "l"(ap[ii].y), "l"(bp[j4].y));
                }
        }
    }

#pragma unroll
    for (int ii = 0; ii < 4; ii++) {
        int g = row0 + tr * 4 + ii;
        if (g >= N_NODES) continue;
#pragma unroll
        for (int jj = 0; jj < TN; jj++) {
            int j = tc + 16 * jj;
            if (j >= n_out) continue;
            float lo, hi;
            asm("mov.b64 {%0, %1}, %2;" : "=f"(lo), "=f"(hi) : "l"(acc[ii][jj]));
            z[(size_t)g * ldz + j] = lo + hi;
        }
    }
}

// ---------------------------------------------------------------------------
// Gather over node range [n0, n1), fused bias + activation:
//   out[n] = act( z[n] + sum_{s in nbrs(n)} z[s] + b )
// ---------------------------------------------------------------------------
template <int ZSEL, int OUTSEL, int NOUT, bool RELU>
__global__ void gcn_gather_kernel(const float* __restrict__ bias,
                                  float* __restrict__ out_p, int n0, int n1) {
    constexpr int NV = (NOUT + 3) / 4;
    const float* z = sel_z<ZSEL>();
    int node = n0 + blockIdx.x * (blockDim.x >> 5) + (threadIdx.x >> 5);
    if (node >= n1) return;
    int lane = threadIdx.x & 31;
    bool act = (NV >= 32) || (lane < NV);
    int beg = g_row[node];
    int end = g_row[node + 1];

    float4 acc = make_float4(0.f, 0.f, 0.f, 0.f);
    float4 bv = make_float4(0.f, 0.f, 0.f, 0.f);
    if (act) {
        acc = *(const float4*)(z + (size_t)node * NOUT + lane * 4);  // self
        bv = *(const float4*)(bias + lane * 4);
    }
    int i = beg;
    for (; i + 4 <= end; i += 4) {
        int s0 = g_esrc[i], s1 = g_esrc[i + 1], s2 = g_esrc[i + 2], s3 = g_esrc[i + 3];
        if (act) {
            float4 v0 = *(const float4*)(z + (size_t)s0 * NOUT + lane * 4);
            float4 v1 = *(const float4*)(z + (size_t)s1 * NOUT + lane * 4);
            float4 v2 = *(const float4*)(z + (size_t)s2 * NOUT + lane * 4);
            float4 v3 = *(const float4*)(z + (size_t)s3 * NOUT + lane * 4);
            acc.x += v0.x + v1.x + v2.x + v3.x;
            acc.y += v0.y + v1.y + v2.y + v3.y;
            acc.z += v0.z + v1.z + v2.z + v3.z;
            acc.w += v0.w + v1.w + v2.w + v3.w;
        }
    }
    for (; i < end; i++) {
        int s = g_esrc[i];
        if (act) {
            float4 v = *(const float4*)(z + (size_t)s * NOUT + lane * 4);
            acc.x += v.x; acc.y += v.y; acc.z += v.z; acc.w += v.w;
        }
    }
    if (act) {
        acc.x += bv.x; acc.y += bv.y; acc.z += bv.z; acc.w += bv.w;
        if (RELU) {
            acc.x = fmaxf(acc.x, 0.f); acc.y = fmaxf(acc.y, 0.f);
            acc.z = fmaxf(acc.z, 0.f); acc.w = fmaxf(acc.w, 0.f);
        }
        float* outp = sel_out<OUTSEL>(out_p);
        *(float4*)(outp + (size_t)node * NOUT + lane * 4) = acc;
    }
}

// ---------------------------------------------------------------------------
extern "C" void kernel_launch(void* const* d_in, const int* in_sizes, int n_in,
                              void* d_out, int out_size) {
    const float* x  = (const float*)d_in[0];
    const int* src  = (const int*)d_in[1];
    const int* dst  = (const int*)d_in[2];
    const float* W0 = (const float*)d_in[3];
    const float* b0 = (const float*)d_in[4];
    const float* W1 = (const float*)d_in[5];
    const float* b1 = (const float*)d_in[6];
    const float* W2 = (const float*)d_in[7];
    const float* b2 = (const float*)d_in[8];
    float* out = (float*)d_out;
    int n_edges = in_sizes[1];

    constexpr int SMEM_BIG   = (64 * 132 + 128 * 132) * 4;  // 101376 B
    constexpr int SMEM_SMALL = (64 * 132 + 64 * 132) * 4;   //  67584 B
    static cudaStream_t s1 = nullptr;
    static cudaEvent_t e_fork, e_csr, eG0, eGa0lo, eG1hi, eGa1lo, eG2hi;
    if (!s1) {
        cudaFuncSetAttribute(gcn_gemm_kernel<0, 0, 128, 8>,
                             cudaFuncAttributeMaxDynamicSharedMemorySize, SMEM_BIG);
        cudaFuncSetAttribute(gcn_gemm_kernel<1, 1, 128, 8>,
                             cudaFuncAttributeMaxDynamicSharedMemorySize, SMEM_BIG);
        cudaFuncSetAttribute(gcn_gemm_kernel<2, 0, 64, 4>,
                             cudaFuncAttributeMaxDynamicSharedMemorySize, SMEM_SMALL);
        cudaStreamCreateWithFlags(&s1, cudaStreamNonBlocking);
        cudaEventCreateWithFlags(&e_fork, cudaEventDisableTiming);
        cudaEventCreateWithFlags(&e_csr, cudaEventDisableTiming);
        cudaEventCreateWithFlags(&eG0, cudaEventDisableTiming);
        cudaEventCreateWithFlags(&eGa0lo, cudaEventDisableTiming);
        cudaEventCreateWithFlags(&eG1hi, cudaEventDisableTiming);
        cudaEventCreateWithFlags(&eGa1lo, cudaEventDisableTiming);
        cudaEventCreateWithFlags(&eG2hi, cudaEventDisableTiming);
    }

    void* cnt_ptr = nullptr;
    cudaGetSymbolAddress(&cnt_ptr, g_cnt);

    const int H = HALF_N;
    int hist_blocks = ((n_edges + 3) / 4 + 255) / 256;
    int gemm_all  = (N_NODES + 63) / 64;
    int gemm_lo   = H / 64;
    int gemm_hi   = (N_NODES - H + 63) / 64;
    int gath_lo   = (H + 7) / 8;
    int gath_hi   = (N_NODES - H + 7) / 8;
    int gath_all  = (N_NODES + 7) / 8;

    // Fork: CSR build on s1, concurrent with GEMM0 on main.
    cudaEventRecord(e_fork, 0);
    cudaStreamWaitEvent(s1, e_fork, 0);
    cudaMemsetAsync(cnt_ptr, 0, N_NODES * sizeof(int), s1);
    gcn_hist_kernel<<<hist_blocks, 256, 0, s1>>>(dst, n_edges);
    gcn_scanA_kernel<<<SCAN_NBLK, SCAN_BLK, 0, s1>>>();
    gcn_scanB_kernel<<<SCAN_NBLK, SCAN_BLK, 0, s1>>>();
    gcn_fill_kernel<<<hist_blocks, 256, 0, s1>>>(src, dst, n_edges);
    cudaEventRecord(e_csr, s1);

    // GEMM0 full: zA = x W0^T
    gcn_gemm_kernel<0, 0, 128, 8><<<gemm_all, 256, SMEM_BIG>>>(x, W0, D, D, 0);
    cudaEventRecord(eG0, 0);

    // ---- Layer-0 boundary: zA -> h1 (g_buf0), pipelined with GEMM1 -> zB ----
    cudaStreamWaitEvent(0, e_csr, 0);
    gcn_gather_kernel<0, 1, 128, true><<<gath_lo, 256>>>(b0, nullptr, 0, H);
    cudaEventRecord(eGa0lo, 0);
    // main: GEMM1_lo (reads h1 lo, writes zB lo)  ||  s1: gather0_hi (reads zA)
    gcn_gemm_kernel<1, 1, 128, 8><<<gemm_lo, 256, SMEM_BIG>>>(nullptr, W1, D, D, 0);
    cudaStreamWaitEvent(s1, eG0, 0);
    cudaStreamWaitEvent(s1, eGa0lo, 0);
    gcn_gather_kernel<0, 1, 128, true><<<gath_hi, 256, 0, s1>>>(b0, nullptr, H, N_NODES);
    gcn_gemm_kernel<1, 1, 128, 8><<<gemm_hi, 256, SMEM_BIG, s1>>>(nullptr, W1, D, D, H);
    cudaEventRecord(eG1hi, s1);

    // ---- Layer-1 boundary: zB -> h2 (g_buf1), pipelined with GEMM2 -> zA ----
    cudaStreamWaitEvent(0, eG1hi, 0);   // zB complete
    gcn_gather_kernel<1, 2, 128, true><<<gath_lo, 256>>>(b1, nullptr, 0, H);
    cudaEventRecord(eGa1lo, 0);
    // main: GEMM2_lo (reads h2 lo, writes zA lo)  ||  s1: gather1_hi (reads zB)
    gcn_gemm_kernel<2, 0, 64, 4><<<gemm_lo, 256, SMEM_SMALL>>>(
        nullptr, W2, N_CLASSES, N_CLASSES, 0);
    cudaStreamWaitEvent(s1, eGa1lo, 0);
    gcn_gather_kernel<1, 2, 128, true><<<gath_hi, 256, 0, s1>>>(b1, nullptr, H, N_NODES);
    gcn_gemm_kernel<2, 0, 64, 4><<<gemm_hi, 256, SMEM_SMALL, s1>>>(
        nullptr, W2, N_CLASSES, N_CLASSES, H);
    cudaEventRecord(eG2hi, s1);

    // ---- Head gather (full, reads zA 40-wide) -> out ----
    cudaStreamWaitEvent(0, eG2hi, 0);
    gcn_gather_kernel<0, 0, N_CLASSES, false><<<gath_all, 256>>>(b2, out, 0, N_NODES);
}

// round 15
// speedup vs baseline: 1.4675x; 1.3605x over previous
#include <cuda_runtime.h>
#include <cuda_bf16.h>
#include <cstdint>

#define N_NODES 50000
#define N_EDGES_MAX 600000
#define D 128
#define N_CLASSES 40

#define SCAN_BLK 1024
#define SCAN_NBLK ((N_NODES + SCAN_BLK - 1) / SCAN_BLK)   // 49

// Scratch (static device globals — no allocations allowed).
// Only dereferenced from DEVICE code; host only takes addresses via API.
__device__ float g_acc[N_NODES * D];   // z = h W^T (GEMM output / gather input)
__device__ float g_buf0[N_NODES * D];  // h1
__device__ float g_buf1[N_NODES * D];  // h2
__device__ int   g_cnt[N_NODES];
__device__ int   g_row[N_NODES + 1];
__device__ int   g_cur[N_NODES];
__device__ int   g_esrc[N_EDGES_MAX];
__device__ int   g_bsum[SCAN_NBLK];

// ---------------------------------------------------------------------------
// CSR build (4 edges per thread)
// ---------------------------------------------------------------------------
__global__ void gcn_hist_kernel(const int* __restrict__ dst, int n_edges) {
    int e0 = (blockIdx.x * blockDim.x + threadIdx.x) * 4;
    if (e0 + 3 < n_edges) {
        int4 d = *(const int4*)(dst + e0);
        atomicAdd(&g_cnt[d.x], 1);
        atomicAdd(&g_cnt[d.y], 1);
        atomicAdd(&g_cnt[d.z], 1);
        atomicAdd(&g_cnt[d.w], 1);
    } else {
        for (int e = e0; e < n_edges; e++) atomicAdd(&g_cnt[dst[e]], 1);
    }
}

__global__ void gcn_scanA_kernel() {
    __shared__ int sh[SCAN_BLK];
    int t = threadIdx.x;
    int idx = blockIdx.x * SCAN_BLK + t;
    int v = (idx < N_NODES) ? g_cnt[idx] : 0;
    sh[t] = v;
    __syncthreads();
    for (int off = 1; off < SCAN_BLK; off <<= 1) {
        int u = (t >= off) ? sh[t - off] : 0;
        __syncthreads();
        sh[t] += u;
        __syncthreads();
    }
    if (idx < N_NODES) g_row[idx] = sh[t] - v;
    if (t == SCAN_BLK - 1) g_bsum[blockIdx.x] = sh[t];
}

__global__ void gcn_scanB_kernel() {
    __shared__ int sh[64];
    __shared__ int s_off;
    int t = threadIdx.x;
    int blk = blockIdx.x;
    if (t < 64) sh[t] = (t < SCAN_NBLK) ? g_bsum[t] : 0;
    __syncthreads();
    if (t == 0) {
        int o = 0;
#pragma unroll 7
        for (int b = 0; b < blk; b++) o += sh[b];
        s_off = o;
    }
    __syncthreads();
    int off = s_off;
    int idx = blk * SCAN_BLK + t;
    if (idx < N_NODES) {
        int r = g_row[idx] + off;
        g_row[idx] = r;
        g_cur[idx] = r;
        if (idx == N_NODES - 1) g_row[N_NODES] = r + g_cnt[idx];
    }
}

__global__ void gcn_fill_kernel(const int* __restrict__ src,
                                const int* __restrict__ dst, int n_edges) {
    int e0 = (blockIdx.x * blockDim.x + threadIdx.x) * 4;
    if (e0 + 3 < n_edges) {
        int4 s = *(const int4*)(src + e0);
        int4 d = *(const int4*)(dst + e0);
        int p0 = atomicAdd(&g_cur[d.x], 1);
        int p1 = atomicAdd(&g_cur[d.y], 1);
        int p2 = atomicAdd(&g_cur[d.z], 1);
        int p3 = atomicAdd(&g_cur[d.w], 1);
        g_esrc[p0] = s.x; g_esrc[p1] = s.y; g_esrc[p2] = s.z; g_esrc[p3] = s.w;
    } else {
        for (int e = e0; e < n_edges; e++) {
            int pos = atomicAdd(&g_cur[dst[e]], 1);
            g_esrc[pos] = src[e];
        }
    }
}

// ---------------------------------------------------------------------------
// Buffer selection by template (device-symbol addresses stay device-side).
// SEL: 0 = param pointer, 1 = g_buf0, 2 = g_buf1
// ---------------------------------------------------------------------------
template <int SEL>
__device__ __forceinline__ const float* sel_in(const float* p) {
    if (SEL == 0) return p;
    if (SEL == 1) return g_buf0;
    return g_buf1;
}
template <int SEL>
__device__ __forceinline__ float* sel_out(float* p) {
    if (SEL == 0) return p;
    if (SEL == 1) return g_buf0;
    return g_buf1;
}

__device__ __forceinline__ float cvt_rna_tf32(float x) {
    float r;
    asm("cvt.rna.tf32.f32 %0, %1;" : "=f"(r) : "f"(x));
    return r;
}

// ---------------------------------------------------------------------------
// tf32 tensor-core GEMM: z = in @ W^T  (no bias/act; commuted aggregation).
// mma.sync.m16n8k8.row.col: A row-major m16k8, B col-major k8n8.
// Our Ws holds W as-is (row j, k-contiguous) = col-major in (k, j) space.
// Fragment loads are conflict-free: bank == lane for a0/b0 patterns.
// Block: 256 thr, BM=64 rows, warps 4x2 (16 rows x NT*8 cols each).
// ---------------------------------------------------------------------------
template <int INSEL, int BN, int NT>
__global__ __launch_bounds__(256, 2)
void gcn_gemm_kernel(const float* __restrict__ in_p,
                     const float* __restrict__ W,
                     int n_out, int ldz) {
    constexpr int BM = 64;
    constexpr int K = D;
    constexpr int LDA = K + 4;   // 132: rows stride 4 banks -> frag loads conflict-free
    extern __shared__ float sm[];
    float* As = sm;              // [BM][LDA]  tf32-rounded activations
    float* Ws = sm + BM * LDA;   // [BN][LDA]  tf32-rounded weights (k-contiguous)
    const uint32_t* Asu = (const uint32_t*)As;
    const uint32_t* Wsu = (const uint32_t*)Ws;

    const float* in = sel_in<INSEL>(in_p);
    int tid = threadIdx.x;
    int row_base = blockIdx.x * BM;

    // Fill Ws (straight copy, coalesced, tf32-rounded)
    for (int i = tid * 4; i < BN * K; i += 256 * 4) {
        int j = i / K, k = i % K;
        float4 v = (j < n_out) ? *(const float4*)(W + (size_t)j * K + k)
                               : make_float4(0.f, 0.f, 0.f, 0.f);
        v.x = cvt_rna_tf32(v.x); v.y = cvt_rna_tf32(v.y);
        v.z = cvt_rna_tf32(v.z); v.w = cvt_rna_tf32(v.w);
        *(float4*)(Ws + j * LDA + k) = v;
    }
    // Fill As
    for (int i = tid * 4; i < BM * K; i += 256 * 4) {
        int r = i / K, k = i % K;
        int g = row_base + r;
        float4 v = (g < N_NODES) ? *(const float4*)(in + (size_t)g * K + k)
                                 : make_float4(0.f, 0.f, 0.f, 0.f);
        v.x = cvt_rna_tf32(v.x); v.y = cvt_rna_tf32(v.y);
        v.z = cvt_rna_tf32(v.z); v.w = cvt_rna_tf32(v.w);
        *(float4*)(As + r * LDA + k) = v;
    }
    __syncthreads();

    int wid = tid >> 5;
    int lane = tid & 31;
    int wr = wid & 3;            // row tile (16 rows)
    int wc = wid >> 2;           // col half
    int r0 = wr * 16;
    int c0 = wc * (NT * 8);
    int gid = lane >> 2;         // groupID
    int tig = lane & 3;          // threadID_in_group

    float acc[NT][4];
#pragma unroll
    for (int nt = 0; nt < NT; nt++)
#pragma unroll
        for (int q = 0; q < 4; q++) acc[nt][q] = 0.f;

#pragma unroll 4
    for (int k0 = 0; k0 < K; k0 += 8) {
        uint32_t a0 = Asu[(r0 + gid) * LDA + k0 + tig];
        uint32_t a1 = Asu[(r0 + gid + 8) * LDA + k0 + tig];
        uint32_t a2 = Asu[(r0 + gid) * LDA + k0 + tig + 4];
        uint32_t a3 = Asu[(r0 + gid + 8) * LDA + k0 + tig + 4];
#pragma unroll
        for (int nt = 0; nt < NT; nt++) {
            uint32_t b0 = Wsu[(c0 + nt * 8 + gid) * LDA + k0 + tig];
            uint32_t b1 = Wsu[(c0 + nt * 8 + gid) * LDA + k0 + tig + 4];
            asm volatile(
                "mma.sync.aligned.m16n8k8.row.col.f32.tf32.tf32.f32 "
                "{%0,%1,%2,%3}, {%4,%5,%6,%7}, {%8,%9}, {%0,%1,%2,%3};"
                : "+f"(acc[nt][0]), "+f"(acc[nt][1]),
                  "+f"(acc[nt][2]), "+f"(acc[nt][3])
                : "r"(a0), "r"(a1), "r"(a2), "r"(a3), "r"(b0), "r"(b1));
        }
    }

    // Epilogue: d0/d1 -> (row gid, cols tig*2, tig*2+1); d2/d3 -> row gid+8.
    int grow0 = row_base + r0 + gid;
    int grow1 = grow0 + 8;
#pragma unroll
    for (int nt = 0; nt < NT; nt++) {
        int j = c0 + nt * 8 + tig * 2;
        if (j < n_out) {
            if (grow0 < N_NODES) {
                float2 v = make_float2(acc[nt][0], acc[nt][1]);
                *(float2*)(g_acc + (size_t)grow0 * ldz + j) = v;
            }
            if (grow1 < N_NODES) {
                float2 v = make_float2(acc[nt][2], acc[nt][3]);
                *(float2*)(g_acc + (size_t)grow1 * ldz + j) = v;
            }
        }
    }
}

// ---------------------------------------------------------------------------
// Gather over z, fused bias + activation:
//   out[n] = act( z[n] + sum_{s in nbrs(n)} z[s] + b )
// ---------------------------------------------------------------------------
template <int OUTSEL, int NOUT, bool RELU>
__global__ void gcn_gather_kernel(const float* __restrict__ bias,
                                  float* __restrict__ out_p) {
    constexpr int NV = (NOUT + 3) / 4;
    int node = blockIdx.x * (blockDim.x >> 5) + (threadIdx.x >> 5);
    if (node >= N_NODES) return;
    int lane = threadIdx.x & 31;
    bool act = (NV >= 32) || (lane < NV);
    int beg = g_row[node];
    int end = g_row[node + 1];

    float4 acc = make_float4(0.f, 0.f, 0.f, 0.f);
    float4 bv = make_float4(0.f, 0.f, 0.f, 0.f);
    if (act) {
        acc = *(const float4*)(g_acc + (size_t)node * NOUT + lane * 4);  // self
        bv = *(const float4*)(bias + lane * 4);
    }
    int i = beg;
    for (; i + 4 <= end; i += 4) {
        int s0 = g_esrc[i], s1 = g_esrc[i + 1], s2 = g_esrc[i + 2], s3 = g_esrc[i + 3];
        if (act) {
            float4 v0 = *(const float4*)(g_acc + (size_t)s0 * NOUT + lane * 4);
            float4 v1 = *(const float4*)(g_acc + (size_t)s1 * NOUT + lane * 4);
            float4 v2 = *(const float4*)(g_acc + (size_t)s2 * NOUT + lane * 4);
            float4 v3 = *(const float4*)(g_acc + (size_t)s3 * NOUT + lane * 4);
            acc.x += v0.x + v1.x + v2.x + v3.x;
            acc.y += v0.y + v1.y + v2.y + v3.y;
            acc.z += v0.z + v1.z + v2.z + v3.z;
            acc.w += v0.w + v1.w + v2.w + v3.w;
        }
    }
    for (; i < end; i++) {
        int s = g_esrc[i];
        if (act) {
            float4 v = *(const float4*)(g_acc + (size_t)s * NOUT + lane * 4);
            acc.x += v.x; acc.y += v.y; acc.z += v.z; acc.w += v.w;
        }
    }
    if (act) {
        acc.x += bv.x; acc.y += bv.y; acc.z += bv.z; acc.w += bv.w;
        if (RELU) {
            acc.x = fmaxf(acc.x, 0.f); acc.y = fmaxf(acc.y, 0.f);
            acc.z = fmaxf(acc.z, 0.f); acc.w = fmaxf(acc.w, 0.f);
        }
        float* outp = sel_out<OUTSEL>(out_p);
        *(float4*)(outp + (size_t)node * NOUT + lane * 4) = acc;
    }
}

// ---------------------------------------------------------------------------
extern "C" void kernel_launch(void* const* d_in, const int* in_sizes, int n_in,
                              void* d_out, int out_size) {
    const float* x  = (const float*)d_in[0];
    const int* src  = (const int*)d_in[1];
    const int* dst  = (const int*)d_in[2];
    const float* W0 = (const float*)d_in[3];
    const float* b0 = (const float*)d_in[4];
    const float* W1 = (const float*)d_in[5];
    const float* b1 = (const float*)d_in[6];
    const float* W2 = (const float*)d_in[7];
    const float* b2 = (const float*)d_in[8];
    float* out = (float*)d_out;
    int n_edges = in_sizes[1];

    constexpr int SMEM_BIG   = (64 * 132 + 128 * 132) * 4;  // 101376 B -> 2 CTA/SM
    constexpr int SMEM_SMALL = (64 * 132 + 64 * 132) * 4;   //  67584 B
    static cudaStream_t s1 = nullptr;
    static cudaEvent_t e_fork = nullptr, e_csr = nullptr;
    if (!s1) {
        cudaFuncSetAttribute(gcn_gemm_kernel<0, 128, 8>,
                             cudaFuncAttributeMaxDynamicSharedMemorySize, SMEM_BIG);
        cudaFuncSetAttribute(gcn_gemm_kernel<1, 128, 8>,
                             cudaFuncAttributeMaxDynamicSharedMemorySize, SMEM_BIG);
        cudaFuncSetAttribute(gcn_gemm_kernel<2, 64, 4>,
                             cudaFuncAttributeMaxDynamicSharedMemorySize, SMEM_SMALL);
        cudaStreamCreateWithFlags(&s1, cudaStreamNonBlocking);
        cudaEventCreateWithFlags(&e_fork, cudaEventDisableTiming);
        cudaEventCreateWithFlags(&e_csr, cudaEventDisableTiming);
    }

    void* cnt_ptr = nullptr;
    cudaGetSymbolAddress(&cnt_ptr, g_cnt);

    int hist_blocks = ((n_edges + 3) / 4 + 255) / 256;
    int gath_blocks = (N_NODES + 7) / 8;
    int gemm_blocks = (N_NODES + 63) / 64;

    // Fork: CSR build on s1, concurrent with GEMM0 on main.
    cudaEventRecord(e_fork, 0);
    cudaStreamWaitEvent(s1, e_fork, 0);
    cudaMemsetAsync(cnt_ptr, 0, N_NODES * sizeof(int), s1);
    gcn_hist_kernel<<<hist_blocks, 256, 0, s1>>>(dst, n_edges);
    gcn_scanA_kernel<<<SCAN_NBLK, SCAN_BLK, 0, s1>>>();
    gcn_scanB_kernel<<<SCAN_NBLK, SCAN_BLK, 0, s1>>>();
    gcn_fill_kernel<<<hist_blocks, 256, 0, s1>>>(src, dst, n_edges);
    cudaEventRecord(e_csr, s1);

    // GEMM0 (independent of CSR): z = x W0^T
    gcn_gemm_kernel<0, 128, 8><<<gemm_blocks, 256, SMEM_BIG>>>(x, W0, D, D);
    cudaStreamWaitEvent(0, e_csr, 0);

    // Layer 0 gather: h1 = relu(z + A z + b0) -> g_buf0
    gcn_gather_kernel<1, 128, true><<<gath_blocks, 256>>>(b0, nullptr);
    // Layer 1: z = h1 W1^T ; h2 = relu(z + A z + b1) -> g_buf1
    gcn_gemm_kernel<1, 128, 8><<<gemm_blocks, 256, SMEM_BIG>>>(nullptr, W1, D, D);
    gcn_gather_kernel<2, 128, true><<<gath_blocks, 256>>>(b1, nullptr);
    // Layer 2 (head): z = h2 W2^T (40-wide) ; out = z + A z + b2
    gcn_gemm_kernel<2, 64, 4><<<gemm_blocks, 256, SMEM_SMALL>>>(
        nullptr, W2, N_CLASSES, N_CLASSES);
    gcn_gather_kernel<0, N_CLASSES, false><<<gath_blocks, 256>>>(b2, out);
}